// round 1
// baseline (speedup 1.0000x reference)
#include <cuda_runtime.h>
#include <cstdint>
#include <cstddef>

// ---------------------------------------------------------------------------
// Problem constants
// ---------------------------------------------------------------------------
constexpr int H_  = 96;     // hidden size
constexpr int G_  = 288;    // 3*H (gates r,z,n)
constexpr int GP  = 289;    // padded gate stride in smem (conflict-free)
constexpr int HP  = 33;     // padded row stride for transposed h/x tiles
constexpr int NB_ = 32;     // batch rows per block
constexpr int T_  = 239;    // seq len
constexpr int B_  = 4096;   // batch
constexpr int L_  = 4;      // layers

constexpr int KIN  = 512;   // fc1 input dim
constexpr int NFC  = 384;   // fc1 output dim (L*H)
constexpr int NFCP = 385;   // padded
constexpr int KC   = 64;    // fc1 K-chunk

constexpr size_t SZ_SEQ = (size_t)T_ * B_ * H_;   // 93,978,624 floats
constexpr size_t SZ_GI  = (size_t)T_ * B_ * G_;   // 281,935,872 floats
constexpr size_t SZ_H0  = (size_t)B_ * NFC;       // 1,572,864 floats

// Scratch (static device memory: allocation-free per harness rules)
__device__ float g_bufA[SZ_SEQ];
__device__ float g_bufB[SZ_SEQ];
__device__ float g_gi  [SZ_GI];
__device__ float g_h0  [SZ_H0];

// ---------------------------------------------------------------------------
// Helpers
// ---------------------------------------------------------------------------
__device__ __forceinline__ float sigf(float x) {
    return 1.0f / (1.0f + __expf(-x));
}
__device__ __forceinline__ float tanh_f(float x) {
    return 2.0f / (1.0f + __expf(-2.0f * x)) - 1.0f;
}

// 32x288 GEMM tile: acc[m][i] += sum_k a_s[k][ry+8m] * w_s[k][cx+32i]
// a_s: [96 x HP] (transposed activations), w_s: [96 x GP] (transposed weights)
__device__ __forceinline__ void gemm32x288(const float* __restrict__ w_s,
                                           const float* __restrict__ a_s,
                                           int cx, int ry, float acc[4][9])
{
#pragma unroll 4
    for (int k = 0; k < H_; ++k) {
        const float a0 = a_s[k * HP + ry +  0];
        const float a1 = a_s[k * HP + ry +  8];
        const float a2 = a_s[k * HP + ry + 16];
        const float a3 = a_s[k * HP + ry + 24];
        const float* wr = w_s + k * GP + cx;
#pragma unroll
        for (int i = 0; i < 9; ++i) {
            const float w = wr[32 * i];
            acc[0][i] = fmaf(a0, w, acc[0][i]);
            acc[1][i] = fmaf(a1, w, acc[1][i]);
            acc[2][i] = fmaf(a2, w, acc[2][i]);
            acc[3][i] = fmaf(a3, w, acc[3][i]);
        }
    }
}

// ---------------------------------------------------------------------------
// fc1: h0 = leaky_relu(concat(z,c) @ fc1_w^T + fc1_b), output [B, 384] flat
// ---------------------------------------------------------------------------
__global__ void __launch_bounds__(256, 1)
fc1_kernel(const float* __restrict__ z, const float* __restrict__ c,
           const float* __restrict__ w, const float* __restrict__ bias,
           float* __restrict__ h0out)
{
    extern __shared__ float sm[];
    float* wc_s = sm;                 // [KC x NFCP]
    float* xc_s = wc_s + KC * NFCP;   // [KC x HP]

    const int tid = threadIdx.x;
    const int cx  = tid & 31;
    const int ry  = tid >> 5;
    const int b0  = blockIdx.x * NB_;

    float acc[4][12];
#pragma unroll
    for (int m = 0; m < 4; ++m)
#pragma unroll
        for (int i = 0; i < 12; ++i) acc[m][i] = 0.f;

    for (int kc = 0; kc < KIN; kc += KC) {
        for (int idx = tid; idx < NFC * KC; idx += 256) {
            int g = idx / KC, kk = idx - g * KC;
            wc_s[kk * NFCP + g] = w[(size_t)g * KIN + kc + kk];
        }
        for (int idx = tid; idx < NB_ * KC; idx += 256) {
            int r = idx / KC, kk = idx - r * KC;
            int k = kc + kk;
            float v = (k < 256) ? z[(size_t)(b0 + r) * 256 + k]
                                : c[(size_t)(b0 + r) * 256 + (k - 256)];
            xc_s[kk * HP + r] = v;
        }
        __syncthreads();
#pragma unroll 4
        for (int kk = 0; kk < KC; ++kk) {
            const float a0 = xc_s[kk * HP + ry +  0];
            const float a1 = xc_s[kk * HP + ry +  8];
            const float a2 = xc_s[kk * HP + ry + 16];
            const float a3 = xc_s[kk * HP + ry + 24];
            const float* wr = wc_s + kk * NFCP + cx;
#pragma unroll
            for (int i = 0; i < 12; ++i) {
                const float wv = wr[32 * i];
                acc[0][i] = fmaf(a0, wv, acc[0][i]);
                acc[1][i] = fmaf(a1, wv, acc[1][i]);
                acc[2][i] = fmaf(a2, wv, acc[2][i]);
                acc[3][i] = fmaf(a3, wv, acc[3][i]);
            }
        }
        __syncthreads();
    }

#pragma unroll
    for (int m = 0; m < 4; ++m) {
        const int r = b0 + ry + 8 * m;
#pragma unroll
        for (int i = 0; i < 12; ++i) {
            const int g = cx + 32 * i;
            float v = acc[m][i] + bias[g];
            v = (v >= 0.f) ? v : 0.2f * v;
            h0out[(size_t)r * NFC + g] = v;
        }
    }
}

// ---------------------------------------------------------------------------
// gi GEMM (parallel over all T*B rows): gi = x @ w_ih^T + b_ih
// ---------------------------------------------------------------------------
__global__ void __launch_bounds__(256, 1)
gi_kernel(const float* __restrict__ w_ih, const float* __restrict__ b_ih,
          const float* __restrict__ x, float* __restrict__ gi)
{
    extern __shared__ float sm[];
    float* wi_s = sm;               // [96 x GP]
    float* x_s  = wi_s + H_ * GP;   // [96 x HP]

    const int tid = threadIdx.x;
    const int cx  = tid & 31;
    const int ry  = tid >> 5;

    for (int idx = tid; idx < G_ * H_; idx += 256) {
        int g = idx / H_, k = idx - g * H_;
        wi_s[k * GP + g] = w_ih[idx];
    }
    float bi[9];
#pragma unroll
    for (int i = 0; i < 9; ++i) bi[i] = b_ih[cx + 32 * i];
    __syncthreads();

    const int ntiles = T_ * B_ / NB_;
    for (int tile = blockIdx.x; tile < ntiles; tile += gridDim.x) {
        const size_t row0 = (size_t)tile * NB_;
        for (int idx = tid; idx < NB_ * H_; idx += 256) {
            int r = idx / H_, k = idx - r * H_;
            x_s[k * HP + r] = x[(row0 + r) * H_ + k];
        }
        __syncthreads();

        float acc[4][9];
#pragma unroll
        for (int m = 0; m < 4; ++m)
#pragma unroll
            for (int i = 0; i < 9; ++i) acc[m][i] = 0.f;

        gemm32x288(wi_s, x_s, cx, ry, acc);

        float* gp = gi + row0 * G_;
#pragma unroll
        for (int m = 0; m < 4; ++m) {
            float* gpr = gp + (size_t)(ry + 8 * m) * G_ + cx;
#pragma unroll
            for (int i = 0; i < 9; ++i) gpr[32 * i] = acc[m][i] + bi[i];
        }
        __syncthreads();
    }
}

// ---------------------------------------------------------------------------
// Sequential GRU scan over T for one layer. Each block owns 32 batch rows.
// gi == nullptr means input sequence is zeros (layer 0): gi = b_ih.
// ---------------------------------------------------------------------------
__global__ void __launch_bounds__(256, 1)
scan_kernel(const float* __restrict__ w_hh, const float* __restrict__ b_hh,
            const float* __restrict__ b_ih, const float* __restrict__ h0,
            const float* __restrict__ gi, float* __restrict__ outp)
{
    extern __shared__ float sm[];
    float* wh_s = sm;                 // [96 x GP]
    float* h_s  = wh_s + H_ * GP;     // [96 x HP]  (h transposed: h_s[k][r])
    float* bh_s = h_s + H_ * HP;      // [288]
    float* bi_s = bh_s + G_;          // [288]

    const int tid = threadIdx.x;
    const int cx  = tid & 31;
    const int ry  = tid >> 5;
    const int b0  = blockIdx.x * NB_;

    for (int idx = tid; idx < G_ * H_; idx += 256) {
        int g = idx / H_, k = idx - g * H_;
        wh_s[k * GP + g] = w_hh[idx];
    }
    for (int idx = tid; idx < G_; idx += 256) {
        bh_s[idx] = b_hh[idx];
        bi_s[idx] = b_ih[idx];
    }
    for (int idx = tid; idx < NB_ * H_; idx += 256) {
        int r = idx / H_, k = idx - r * H_;
        h_s[k * HP + r] = h0[(size_t)(b0 + r) * H_ + k];
    }
    __syncthreads();

    float bh[9], bi[9];
#pragma unroll
    for (int i = 0; i < 9; ++i) {
        bh[i] = bh_s[cx + 32 * i];
        bi[i] = bi_s[cx + 32 * i];
    }

    for (int t = 0; t < T_; ++t) {
        // Prefetch gi for this step (no dependency on h -> hidden under GEMM)
        float giv[4][9];
        if (gi != nullptr) {
            const float* gp = gi + ((size_t)t * B_ + b0) * G_;
#pragma unroll
            for (int m = 0; m < 4; ++m) {
                const float* gpr = gp + (size_t)(ry + 8 * m) * G_ + cx;
#pragma unroll
                for (int i = 0; i < 9; ++i) giv[m][i] = gpr[32 * i];
            }
        } else {
#pragma unroll
            for (int m = 0; m < 4; ++m)
#pragma unroll
                for (int i = 0; i < 9; ++i) giv[m][i] = bi[i];
        }

        float acc[4][9];
#pragma unroll
        for (int m = 0; m < 4; ++m)
#pragma unroll
            for (int i = 0; i < 9; ++i) acc[m][i] = 0.f;

        gemm32x288(wh_s, h_s, cx, ry, acc);   // gh (without bh)

        __syncthreads();  // all GEMM reads of h_s done before updates

        float* op = outp + ((size_t)t * B_ + b0) * H_;
#pragma unroll
        for (int m = 0; m < 4; ++m) {
            const int r = ry + 8 * m;
#pragma unroll
            for (int ii = 0; ii < 3; ++ii) {
                const int j = cx + 32 * ii;  // j, j+96, j+192 are this thread's cols ii, ii+3, ii+6
                const float rg = sigf(giv[m][ii]     + acc[m][ii]     + bh[ii]);
                const float zg = sigf(giv[m][ii + 3] + acc[m][ii + 3] + bh[ii + 3]);
                const float ng = tanh_f(giv[m][ii + 6] + rg * (acc[m][ii + 6] + bh[ii + 6]));
                const float hold = h_s[j * HP + r];      // only owner touches this slot
                const float hnew = (1.f - zg) * ng + zg * hold;
                h_s[j * HP + r] = hnew;
                op[(size_t)r * H_ + j] = hnew;           // coalesced over cx
            }
        }
        __syncthreads();  // h updates visible before next step's GEMM
    }
}

// ---------------------------------------------------------------------------
// [T,B,H] -> [B,H,T] transpose (smem tiled)
// ---------------------------------------------------------------------------
__global__ void transpose_kernel(const float* __restrict__ in, float* __restrict__ outp)
{
    __shared__ float tile[32][33];
    const int b  = blockIdx.z;
    const int j0 = blockIdx.y * 32;   // 0,32,64 (96 = 3*32, always in range)
    const int t0 = blockIdx.x * 32;
    const int tx = threadIdx.x, ty = threadIdx.y;

#pragma unroll
    for (int yy = ty; yy < 32; yy += 8) {
        const int t = t0 + yy;
        if (t < T_) tile[yy][tx] = in[((size_t)t * B_ + b) * H_ + j0 + tx];
    }
    __syncthreads();
#pragma unroll
    for (int yy = ty; yy < 32; yy += 8) {
        const int t = t0 + tx;
        const int j = j0 + yy;
        if (t < T_) outp[((size_t)b * H_ + j) * T_ + t] = tile[tx][yy];
    }
}

// ---------------------------------------------------------------------------
// Launch
// ---------------------------------------------------------------------------
extern "C" void kernel_launch(void* const* d_in, const int* in_sizes, int n_in,
                              void* d_out, int out_size)
{
    const float* z     = (const float*)d_in[0];
    const float* c     = (const float*)d_in[1];
    const float* fc1_w = (const float*)d_in[2];
    const float* fc1_b = (const float*)d_in[3];
    const float* w_ih  = (const float*)d_in[4];   // [L,288,96]
    const float* w_hh  = (const float*)d_in[5];   // [L,288,96]
    const float* b_ih  = (const float*)d_in[6];   // [L,288]
    const float* b_hh  = (const float*)d_in[7];   // [L,288]
    float* out = (float*)d_out;

    float *bufA, *bufB, *giBuf, *h0Buf;
    cudaGetSymbolAddress((void**)&bufA,  g_bufA);
    cudaGetSymbolAddress((void**)&bufB,  g_bufB);
    cudaGetSymbolAddress((void**)&giBuf, g_gi);
    cudaGetSymbolAddress((void**)&h0Buf, g_h0);

    const size_t scanSm = (size_t)(H_ * GP + H_ * HP + 2 * G_) * sizeof(float);  // ~126 KB
    const size_t giSm   = (size_t)(H_ * GP + H_ * HP) * sizeof(float);           // ~124 KB
    const size_t fcSm   = (size_t)(KC * NFCP + KC * HP) * sizeof(float);         // ~107 KB
    cudaFuncSetAttribute(scan_kernel, cudaFuncAttributeMaxDynamicSharedMemorySize, (int)scanSm);
    cudaFuncSetAttribute(gi_kernel,   cudaFuncAttributeMaxDynamicSharedMemorySize, (int)giSm);
    cudaFuncSetAttribute(fc1_kernel,  cudaFuncAttributeMaxDynamicSharedMemorySize, (int)fcSm);

    const int nblk = B_ / NB_;  // 128

    fc1_kernel<<<nblk, 256, fcSm>>>(z, c, fc1_w, fc1_b, h0Buf);

    // layer 0: input is zeros -> gi = b_ih (nullptr path)
    scan_kernel<<<nblk, 256, scanSm>>>(w_hh, b_hh, b_ih, h0Buf, nullptr, bufA);

    // layer 1
    gi_kernel<<<592, 256, giSm>>>(w_ih + 1 * (size_t)G_ * H_, b_ih + 1 * G_, bufA, giBuf);
    scan_kernel<<<nblk, 256, scanSm>>>(w_hh + 1 * (size_t)G_ * H_, b_hh + 1 * G_,
                                       b_ih + 1 * G_, h0Buf + 1 * (size_t)B_ * H_, giBuf, bufB);
    // layer 2
    gi_kernel<<<592, 256, giSm>>>(w_ih + 2 * (size_t)G_ * H_, b_ih + 2 * G_, bufB, giBuf);
    scan_kernel<<<nblk, 256, scanSm>>>(w_hh + 2 * (size_t)G_ * H_, b_hh + 2 * G_,
                                       b_ih + 2 * G_, h0Buf + 2 * (size_t)B_ * H_, giBuf, bufA);
    // layer 3
    gi_kernel<<<592, 256, giSm>>>(w_ih + 3 * (size_t)G_ * H_, b_ih + 3 * G_, bufA, giBuf);
    scan_kernel<<<nblk, 256, scanSm>>>(w_hh + 3 * (size_t)G_ * H_, b_hh + 3 * G_,
                                       b_ih + 3 * G_, h0Buf + 3 * (size_t)B_ * H_, giBuf, bufB);

    transpose_kernel<<<dim3(8, 3, B_), dim3(32, 8)>>>(bufB, out);
}

// round 2
// speedup vs baseline: 2.0869x; 2.0869x over previous
#include <cuda_runtime.h>
#include <cuda_bf16.h>
#include <cstdint>
#include <cstddef>

// ---------------------------------------------------------------------------
constexpr int H_  = 96;
constexpr int G_  = 288;
constexpr int T_  = 239;
constexpr int B_  = 4096;
constexpr int NB_ = 32;

constexpr int HP2 = 104;   // bf16 row pitch for ldmatrix tiles (16B-mult, conflict-ok)
constexpr int GHP = 297;   // f32 gh pitch (odd -> conflict-free column writes)

constexpr int KIN  = 512;
constexpr int NFC  = 384;
constexpr int NFCP = 385;
constexpr int KC   = 64;
constexpr int HPf  = 33;

constexpr size_t SZ_SEQ = (size_t)T_ * B_ * H_;
constexpr size_t SZ_GI  = (size_t)T_ * B_ * G_;
constexpr size_t SZ_H0  = (size_t)B_ * NFC;

__device__ float g_bufA[SZ_SEQ];
__device__ float g_bufB[SZ_SEQ];
__device__ float g_gi  [SZ_GI];
__device__ float g_h0  [SZ_H0];

// ---------------------------------------------------------------------------
__device__ __forceinline__ float sigf(float x)   { return 1.0f / (1.0f + __expf(-x)); }
__device__ __forceinline__ float tanh_f(float x) { return 2.0f / (1.0f + __expf(-2.0f * x)) - 1.0f; }

__device__ __forceinline__ uint32_t pack_bf16(__nv_bfloat16 a, __nv_bfloat16 b) {
    return (uint32_t)__bfloat16_as_ushort(a) | ((uint32_t)__bfloat16_as_ushort(b) << 16);
}
__device__ __forceinline__ void split2(float x, __nv_bfloat16& h, __nv_bfloat16& l) {
    h = __float2bfloat16(x);
    l = __float2bfloat16(x - __bfloat162float(h));
}

__device__ __forceinline__ void mma16816(float c[4], const uint32_t a[4], const uint32_t b[2]) {
    asm volatile(
        "mma.sync.aligned.m16n8k16.row.col.f32.bf16.bf16.f32 "
        "{%0,%1,%2,%3}, {%4,%5,%6,%7}, {%8,%9}, {%0,%1,%2,%3};"
        : "+f"(c[0]), "+f"(c[1]), "+f"(c[2]), "+f"(c[3])
        : "r"(a[0]), "r"(a[1]), "r"(a[2]), "r"(a[3]), "r"(b[0]), "r"(b[1]));
}
__device__ __forceinline__ void ldsm4(uint32_t r[4], uint32_t addr) {
    asm volatile("ldmatrix.sync.aligned.m8n8.x4.shared.b16 {%0,%1,%2,%3}, [%4];"
                 : "=r"(r[0]), "=r"(r[1]), "=r"(r[2]), "=r"(r[3]) : "r"(addr));
}

// Per-thread weight fragments for this warp's 32 output cols (4 n-tiles, 6 k-tiles)
struct BFrags { uint32_t hi[6][4][2]; uint32_t lo[6][4][2]; };

__device__ __forceinline__ void load_bfrags(const float* __restrict__ w, int lane, int ncb, BFrags& bf) {
#pragma unroll
    for (int kt = 0; kt < 6; ++kt)
#pragma unroll
        for (int nt = 0; nt < 4; ++nt) {
            const int g  = ncb + nt * 8 + (lane >> 2);
            const int k0 = kt * 16 + (lane & 3) * 2;
            const float* p = w + (size_t)g * H_ + k0;
            float w0 = p[0], w1 = p[1], w2 = p[8], w3 = p[9];
            __nv_bfloat16 h0, h1, h2, h3, l0, l1, l2, l3;
            split2(w0, h0, l0); split2(w1, h1, l1);
            split2(w2, h2, l2); split2(w3, h3, l3);
            bf.hi[kt][nt][0] = pack_bf16(h0, h1);
            bf.hi[kt][nt][1] = pack_bf16(h2, h3);
            bf.lo[kt][nt][0] = pack_bf16(l0, l1);
            bf.lo[kt][nt][1] = pack_bf16(l2, l3);
        }
}

// Split-bf16 GEMM: c[mt][nt] += Ahi*Bhi + Ahi*Blo + Alo*Bhi over 6 k-tiles.
// aHi/aLo: shared-space byte addresses (per-lane ldmatrix base for mt=0, kt=0).
__device__ __forceinline__ void gemm_step(uint32_t aHi, uint32_t aLo,
                                          const BFrags& bf, float c[2][4][4]) {
#pragma unroll
    for (int kt = 0; kt < 6; ++kt) {
        const uint32_t o = (uint32_t)(kt * 16 * 2);
        uint32_t ah0[4], ah1[4], al0[4], al1[4];
        ldsm4(ah0, aHi + o);
        ldsm4(ah1, aHi + o + 16 * HP2 * 2);
        ldsm4(al0, aLo + o);
        ldsm4(al1, aLo + o + 16 * HP2 * 2);
#pragma unroll
        for (int nt = 0; nt < 4; ++nt) {
            mma16816(c[0][nt], ah0, bf.hi[kt][nt]);
            mma16816(c[0][nt], ah0, bf.lo[kt][nt]);
            mma16816(c[0][nt], al0, bf.hi[kt][nt]);
            mma16816(c[1][nt], ah1, bf.hi[kt][nt]);
            mma16816(c[1][nt], ah1, bf.lo[kt][nt]);
            mma16816(c[1][nt], al1, bf.hi[kt][nt]);
        }
    }
}

// ---------------------------------------------------------------------------
// GRU scan, tensor-core version. One block = 32 batch rows, 288 threads.
// ---------------------------------------------------------------------------
template <bool HAS_GI>
__global__ void __launch_bounds__(288, 1)
scan_mma(const float* __restrict__ w_hh, const float* __restrict__ b_hh,
         const float* __restrict__ b_ih, const float* __restrict__ h0,
         const float* __restrict__ gi, float* __restrict__ outp)
{
    extern __shared__ char smraw[];
    float* gh = (float*)smraw;                              // [32][GHP]
    float* hf = gh + 32 * GHP;                              // [32][96] fp32 h
    __nv_bfloat16* hhi = (__nv_bfloat16*)(hf + 32 * 96);    // [32][HP2]
    __nv_bfloat16* hlo = hhi + 32 * HP2;                    // [32][HP2]

    const int tid  = threadIdx.x;
    const int lane = tid & 31;
    const int wid  = tid >> 5;      // 0..8
    const int ncb  = wid * 32;      // warp col base in [0,288)
    const int b0   = blockIdx.x * NB_;

    BFrags bf;
    load_bfrags(w_hh, lane, ncb, bf);

    float bhv[4][2];
#pragma unroll
    for (int nt = 0; nt < 4; ++nt) {
        const int col = ncb + nt * 8 + 2 * (lane & 3);
        bhv[nt][0] = b_hh[col];
        bhv[nt][1] = b_hh[col + 1];
    }

    // elementwise mapping: j fixed per thread, rows r = r0 + 3i
    const int j  = tid % 96;
    const int r0 = tid / 96;
    const float bi0 = b_ih[j], bi1 = b_ih[j + 96], bi2 = b_ih[j + 192];

    // init h state
#pragma unroll
    for (int i = 0; i < 11; ++i) {
        const int r = r0 + 3 * i;
        if (r < 32) {
            const float v = h0[(size_t)(b0 + r) * H_ + j];
            hf[r * 96 + j] = v;
            __nv_bfloat16 h, l; split2(v, h, l);
            hhi[r * HP2 + j] = h; hlo[r * HP2 + j] = l;
        }
    }
    __syncthreads();

    // ldmatrix per-lane addresses (mt=0, kt=0 base)
    const int arow = (lane & 7) + ((lane >> 3) & 1) * 8;
    const int acol = ((lane >> 4) & 1) * 8;
    const uint32_t aHi = (uint32_t)__cvta_generic_to_shared(hhi) + (uint32_t)((arow * HP2 + acol) * 2);
    const uint32_t aLo = (uint32_t)__cvta_generic_to_shared(hlo) + (uint32_t)((arow * HP2 + acol) * 2);

    const int crow = lane >> 2;
    const int ccol = ncb + 2 * (lane & 3);

    for (int t = 0; t < T_; ++t) {
        // prefetch gi for this step (hidden under the GEMM)
        float gv0[11], gv1[11], gv2[11];
        if (HAS_GI) {
            const float* gp = gi + ((size_t)t * B_ + b0) * G_;
#pragma unroll
            for (int i = 0; i < 11; ++i) {
                const int r = r0 + 3 * i;
                if (r < 32) {
                    const float* q = gp + (size_t)r * G_ + j;
                    gv0[i] = q[0]; gv1[i] = q[96]; gv2[i] = q[192];
                }
            }
        }

        float c[2][4][4];
#pragma unroll
        for (int mt = 0; mt < 2; ++mt)
#pragma unroll
            for (int nt = 0; nt < 4; ++nt)
#pragma unroll
                for (int q = 0; q < 4; ++q) c[mt][nt][q] = 0.f;

        gemm_step(aHi, aLo, bf, c);

        // gh = h @ whT + bh (bias folded here)
#pragma unroll
        for (int mt = 0; mt < 2; ++mt)
#pragma unroll
            for (int nt = 0; nt < 4; ++nt) {
                const int rowa = mt * 16 + crow;
                const int col  = ccol + nt * 8;
                gh[rowa * GHP + col]           = c[mt][nt][0] + bhv[nt][0];
                gh[rowa * GHP + col + 1]       = c[mt][nt][1] + bhv[nt][1];
                gh[(rowa + 8) * GHP + col]     = c[mt][nt][2] + bhv[nt][0];
                gh[(rowa + 8) * GHP + col + 1] = c[mt][nt][3] + bhv[nt][1];
            }
        __syncthreads();

        float* op = outp + ((size_t)t * B_ + b0) * H_;
#pragma unroll
        for (int i = 0; i < 11; ++i) {
            const int r = r0 + 3 * i;
            if (r < 32) {
                const float g0 = (HAS_GI ? gv0[i] : bi0) + gh[r * GHP + j];
                const float g1 = (HAS_GI ? gv1[i] : bi1) + gh[r * GHP + j + 96];
                const float hn = gh[r * GHP + j + 192];
                const float rg = sigf(g0);
                const float zg = sigf(g1);
                const float ng = tanh_f((HAS_GI ? gv2[i] : bi2) + rg * hn);
                const float hold = hf[r * 96 + j];
                const float hnew = ng + zg * (hold - ng);
                hf[r * 96 + j] = hnew;
                op[(size_t)r * H_ + j] = hnew;
                __nv_bfloat16 h, l; split2(hnew, h, l);
                hhi[r * HP2 + j] = h; hlo[r * HP2 + j] = l;
            }
        }
        __syncthreads();
    }
}

// ---------------------------------------------------------------------------
// gi = x @ w_ih^T + b_ih over all T*B rows (tensor-core, persistent blocks)
// ---------------------------------------------------------------------------
__global__ void __launch_bounds__(288, 1)
gi_mma(const float* __restrict__ w_ih, const float* __restrict__ b_ih,
       const float* __restrict__ x, float* __restrict__ gi)
{
    __shared__ __align__(16) __nv_bfloat16 xbuf[2 * 32 * HP2];
    __nv_bfloat16* xhi = xbuf;
    __nv_bfloat16* xlo = xbuf + 32 * HP2;

    const int tid  = threadIdx.x;
    const int lane = tid & 31;
    const int wid  = tid >> 5;
    const int ncb  = wid * 32;

    BFrags bf;
    load_bfrags(w_ih, lane, ncb, bf);

    float bv[4][2];
#pragma unroll
    for (int nt = 0; nt < 4; ++nt) {
        const int col = ncb + nt * 8 + 2 * (lane & 3);
        bv[nt][0] = b_ih[col];
        bv[nt][1] = b_ih[col + 1];
    }

    const int j  = tid % 96;
    const int r0 = tid / 96;

    const int arow = (lane & 7) + ((lane >> 3) & 1) * 8;
    const int acol = ((lane >> 4) & 1) * 8;
    const uint32_t aHi = (uint32_t)__cvta_generic_to_shared(xhi) + (uint32_t)((arow * HP2 + acol) * 2);
    const uint32_t aLo = (uint32_t)__cvta_generic_to_shared(xlo) + (uint32_t)((arow * HP2 + acol) * 2);

    const int crow = lane >> 2;
    const int ccol = ncb + 2 * (lane & 3);

    const int ntiles = T_ * B_ / NB_;
    for (int tile = blockIdx.x; tile < ntiles; tile += gridDim.x) {
        const size_t row0 = (size_t)tile * NB_;
#pragma unroll
        for (int i = 0; i < 11; ++i) {
            const int r = r0 + 3 * i;
            if (r < 32) {
                const float v = x[(row0 + r) * H_ + j];
                __nv_bfloat16 h, l; split2(v, h, l);
                xhi[r * HP2 + j] = h; xlo[r * HP2 + j] = l;
            }
        }
        __syncthreads();

        float c[2][4][4];
#pragma unroll
        for (int mt = 0; mt < 2; ++mt)
#pragma unroll
            for (int nt = 0; nt < 4; ++nt)
#pragma unroll
                for (int q = 0; q < 4; ++q) c[mt][nt][q] = 0.f;

        gemm_step(aHi, aLo, bf, c);

#pragma unroll
        for (int mt = 0; mt < 2; ++mt)
#pragma unroll
            for (int nt = 0; nt < 4; ++nt) {
                const size_t ra = row0 + mt * 16 + crow;
                const int col   = ccol + nt * 8;
                float2 v01 = make_float2(c[mt][nt][0] + bv[nt][0], c[mt][nt][1] + bv[nt][1]);
                float2 v23 = make_float2(c[mt][nt][2] + bv[nt][0], c[mt][nt][3] + bv[nt][1]);
                *(float2*)(gi + ra * G_ + col)       = v01;
                *(float2*)(gi + (ra + 8) * G_ + col) = v23;
            }
        __syncthreads();
    }
}

// ---------------------------------------------------------------------------
// fc1 (fp32, tiny) — unchanged from round 1
// ---------------------------------------------------------------------------
__global__ void __launch_bounds__(256, 1)
fc1_kernel(const float* __restrict__ z, const float* __restrict__ c,
           const float* __restrict__ w, const float* __restrict__ bias,
           float* __restrict__ h0out)
{
    extern __shared__ float sm[];
    float* wc_s = sm;
    float* xc_s = wc_s + KC * NFCP;

    const int tid = threadIdx.x;
    const int cx  = tid & 31;
    const int ry  = tid >> 5;
    const int b0  = blockIdx.x * NB_;

    float acc[4][12];
#pragma unroll
    for (int m = 0; m < 4; ++m)
#pragma unroll
        for (int i = 0; i < 12; ++i) acc[m][i] = 0.f;

    for (int kc = 0; kc < KIN; kc += KC) {
        for (int idx = tid; idx < NFC * KC; idx += 256) {
            int g = idx / KC, kk = idx - g * KC;
            wc_s[kk * NFCP + g] = w[(size_t)g * KIN + kc + kk];
        }
        for (int idx = tid; idx < NB_ * KC; idx += 256) {
            int r = idx / KC, kk = idx - r * KC;
            int k = kc + kk;
            float v = (k < 256) ? z[(size_t)(b0 + r) * 256 + k]
                                : c[(size_t)(b0 + r) * 256 + (k - 256)];
            xc_s[kk * HPf + r] = v;
        }
        __syncthreads();
#pragma unroll 4
        for (int kk = 0; kk < KC; ++kk) {
            const float a0 = xc_s[kk * HPf + ry +  0];
            const float a1 = xc_s[kk * HPf + ry +  8];
            const float a2 = xc_s[kk * HPf + ry + 16];
            const float a3 = xc_s[kk * HPf + ry + 24];
            const float* wr = wc_s + kk * NFCP + cx;
#pragma unroll
            for (int i = 0; i < 12; ++i) {
                const float wv = wr[32 * i];
                acc[0][i] = fmaf(a0, wv, acc[0][i]);
                acc[1][i] = fmaf(a1, wv, acc[1][i]);
                acc[2][i] = fmaf(a2, wv, acc[2][i]);
                acc[3][i] = fmaf(a3, wv, acc[3][i]);
            }
        }
        __syncthreads();
    }

#pragma unroll
    for (int m = 0; m < 4; ++m) {
        const int r = b0 + ry + 8 * m;
#pragma unroll
        for (int i = 0; i < 12; ++i) {
            const int g = cx + 32 * i;
            float v = acc[m][i] + bias[g];
            v = (v >= 0.f) ? v : 0.2f * v;
            h0out[(size_t)r * NFC + g] = v;
        }
    }
}

// ---------------------------------------------------------------------------
// [T,B,H] -> [B,H,T] transpose
// ---------------------------------------------------------------------------
__global__ void transpose_kernel(const float* __restrict__ in, float* __restrict__ outp)
{
    __shared__ float tile[32][33];
    const int b  = blockIdx.z;
    const int j0 = blockIdx.y * 32;
    const int t0 = blockIdx.x * 32;
    const int tx = threadIdx.x, ty = threadIdx.y;

#pragma unroll
    for (int yy = ty; yy < 32; yy += 8) {
        const int t = t0 + yy;
        if (t < T_) tile[yy][tx] = in[((size_t)t * B_ + b) * H_ + j0 + tx];
    }
    __syncthreads();
#pragma unroll
    for (int yy = ty; yy < 32; yy += 8) {
        const int t = t0 + tx;
        const int j = j0 + yy;
        if (t < T_) outp[((size_t)b * H_ + j) * T_ + t] = tile[tx][yy];
    }
}

// ---------------------------------------------------------------------------
extern "C" void kernel_launch(void* const* d_in, const int* in_sizes, int n_in,
                              void* d_out, int out_size)
{
    const float* z     = (const float*)d_in[0];
    const float* c     = (const float*)d_in[1];
    const float* fc1_w = (const float*)d_in[2];
    const float* fc1_b = (const float*)d_in[3];
    const float* w_ih  = (const float*)d_in[4];
    const float* w_hh  = (const float*)d_in[5];
    const float* b_ih  = (const float*)d_in[6];
    const float* b_hh  = (const float*)d_in[7];
    float* out = (float*)d_out;

    float *bufA, *bufB, *giBuf, *h0Buf;
    cudaGetSymbolAddress((void**)&bufA,  g_bufA);
    cudaGetSymbolAddress((void**)&bufB,  g_bufB);
    cudaGetSymbolAddress((void**)&giBuf, g_gi);
    cudaGetSymbolAddress((void**)&h0Buf, g_h0);

    const size_t scanSm = (size_t)(32 * GHP + 32 * 96) * sizeof(float)
                        + (size_t)(2 * 32 * HP2) * sizeof(__nv_bfloat16);   // ~63.6 KB
    const size_t fcSm   = (size_t)(KC * NFCP + KC * HPf) * sizeof(float);

    cudaFuncSetAttribute(scan_mma<false>, cudaFuncAttributeMaxDynamicSharedMemorySize, (int)scanSm);
    cudaFuncSetAttribute(scan_mma<true>,  cudaFuncAttributeMaxDynamicSharedMemorySize, (int)scanSm);
    cudaFuncSetAttribute(fc1_kernel,      cudaFuncAttributeMaxDynamicSharedMemorySize, (int)fcSm);

    const int nblk = B_ / NB_;  // 128

    fc1_kernel<<<nblk, 256, fcSm>>>(z, c, fc1_w, fc1_b, h0Buf);

    // layer 0 (input zeros: gi == b_ih)
    scan_mma<false><<<nblk, 288, scanSm>>>(w_hh, b_hh, b_ih, h0Buf, nullptr, bufA);

    // layers 1..3
    const float* srcs[3] = {bufA, bufB, bufA};
    float*       dsts[3] = {bufB, bufA, bufB};
    for (int l = 1; l < 4; ++l) {
        const size_t wo = (size_t)l * G_ * H_;
        const size_t bo = (size_t)l * G_;
        gi_mma<<<148, 288>>>(w_ih + wo, b_ih + bo, srcs[l - 1], giBuf);
        scan_mma<true><<<nblk, 288, scanSm>>>(w_hh + wo, b_hh + bo, b_ih + bo,
                                              h0Buf + (size_t)l * B_ * H_, giBuf, dsts[l - 1]);
    }

    transpose_kernel<<<dim3(8, 3, B_), dim3(32, 8)>>>(bufB, out);
}